// round 10
// baseline (speedup 1.0000x reference)
#include <cuda_runtime.h>
#include <cstdint>

// out = relu( GroupNorm32( Wv @ feat + bv, gn_v_g, gn_v_b ) )
// (softmax-weighted sum in the reference is identity: v is constant along the
//  softmax axis and softmax rows sum to 1).
//
// feat [2,128,512], Wv [128,128], out [2,128,512].
// Grid: 64 blocks = B(2) x group(32); one CTA owns a full GN group.
// 512 threads: tx = 128 float4 columns, ty = 4 cc-quarters.
// Mainloop uses PACKED fma.rn.f32x2 (FFMA2): weights pre-duplicated (w,w) as
// u64 in smem, feat loaded as ulonglong2 -> 256 FFMA2-inst/thread instead of
// 512 FFMA  => per-SMSP issue floor ~2900 cyc vs ~5120.  Bit-identical math.
// Post-loop: 1 smem fold + redundant stats (2 syncs), no clusters/atomics.

#define C_CH     128
#define NPT      512
#define CH_PER_G 4
#define EPS_GN   1e-5f
#define NTHREADS 512
#define ROW4     (NPT / 4)     // 128 float4 per feat row
#define CC_PER_T (C_CH / 4)    // 32 cc per ty
#define CHUNK    8
#define NWARPS   (NTHREADS / 32)

typedef unsigned long long u64;

#define FMA2(d, a, b, c) \
    asm("fma.rn.f32x2 %0, %1, %2, %3;" : "=l"(d) : "l"(a), "l"(b), "l"(c))

__device__ __forceinline__ float4 f4add(float4 a, float4 b) {
    a.x += b.x; a.y += b.y; a.z += b.z; a.w += b.w; return a;
}

__device__ __forceinline__ u64 pack2(float lo, float hi) {
    u64 r;
    asm("mov.b64 %0, {%1, %2};" : "=l"(r) : "f"(lo), "f"(hi));
    return r;
}

__device__ __forceinline__ float2 unpack2(u64 v) {
    float2 r;
    asm("mov.b64 {%0, %1}, %2;" : "=f"(r.x), "=f"(r.y) : "l"(v));
    return r;
}

__global__ __launch_bounds__(NTHREADS, 1)
void fused_v_gn_relu_kernel(const float* __restrict__ feat,
                            const float* __restrict__ Wv,
                            const float* __restrict__ bv,
                            const float* __restrict__ gamma,
                            const float* __restrict__ beta,
                            float* __restrict__ out) {
    const int g  = blockIdx.x & 31;   // group 0..31
    const int b  = blockIdx.x >> 5;   // batch 0..1
    const int c0 = g * CH_PER_G;
    const int t  = threadIdx.x;       // 0..511
    const int tx = t & 127;           // float4 column (0..127)
    const int ty = t >> 7;            // cc quarter (0..3)

    __shared__ u64    wt2_s[C_CH * CH_PER_G];         // packed (w,w), 4KB
    __shared__ float4 part_s[4 * CH_PER_G * ROW4];    // [ty][c][col], 32KB
    __shared__ float  red_s[2 * NWARPS];

    // Stage packed duplicated weights: wt2_s[cc*4 + c] = (w,w),
    // w = Wv[(c0+c)*128 + cc].  One element per thread.
    {
        const float w = Wv[(c0 + (t & 3)) * C_CH + (t >> 2)];
        wt2_s[t] = pack2(w, w);
    }

    // feat rows as ulonglong2 (16B = 4 floats; .x packs pts {0,1}, .y {2,3}).
    const ulonglong2* fp = (const ulonglong2*)(feat + (size_t)b * C_CH * NPT)
                           + (size_t)(ty * CC_PER_T) * ROW4 + tx;

    // Prime double buffer before the sync (LDG latency overlaps staging).
    ulonglong2 cur[CHUNK], nxt[CHUNK];
    #pragma unroll
    for (int i = 0; i < CHUNK; i++) cur[i] = fp[i * ROW4];

    __syncthreads();

    const int wbase = ty * CC_PER_T;

    // Packed accumulators: acc2[c][p], p=0 -> pts{0,1}, p=1 -> pts{2,3}.
    u64 acc2[CH_PER_G][2];
    #pragma unroll
    for (int c = 0; c < CH_PER_G; c++) {
        const float bvc = (ty == 0) ? bv[c0 + c] : 0.f;
        const u64 p = pack2(bvc, bvc);
        acc2[c][0] = p; acc2[c][1] = p;
    }

    // Mainloop: 4 chunks of (8 LDG.128 + 16 LDS.128 + 64 FFMA2).
    #pragma unroll
    for (int cb = 0; cb < CC_PER_T; cb += CHUNK) {
        if (cb + CHUNK < CC_PER_T) {
            #pragma unroll
            for (int i = 0; i < CHUNK; i++)
                nxt[i] = fp[(cb + CHUNK + i) * ROW4];
        }
        #pragma unroll
        for (int i = 0; i < CHUNK; i++) {
            const ulonglong2* wp =
                (const ulonglong2*)&wt2_s[(wbase + cb + i) * CH_PER_G];
            const ulonglong2 wa = wp[0];   // ch0, ch1 (broadcast LDS.128)
            const ulonglong2 wb = wp[1];   // ch2, ch3
            const ulonglong2 f  = cur[i];
            FMA2(acc2[0][0], wa.x, f.x, acc2[0][0]);
            FMA2(acc2[0][1], wa.x, f.y, acc2[0][1]);
            FMA2(acc2[1][0], wa.y, f.x, acc2[1][0]);
            FMA2(acc2[1][1], wa.y, f.y, acc2[1][1]);
            FMA2(acc2[2][0], wb.x, f.x, acc2[2][0]);
            FMA2(acc2[2][1], wb.x, f.y, acc2[2][1]);
            FMA2(acc2[3][0], wb.y, f.x, acc2[3][0]);
            FMA2(acc2[3][1], wb.y, f.y, acc2[3][1]);
        }
        #pragma unroll
        for (int i = 0; i < CHUNK; i++) cur[i] = nxt[i];
    }

    // Publish cc-quarter partials (unpack to float4; same bits as before).
    #pragma unroll
    for (int c = 0; c < CH_PER_G; c++) {
        const float2 lo = unpack2(acc2[c][0]);
        const float2 hi = unpack2(acc2[c][1]);
        float4 a; a.x = lo.x; a.y = lo.y; a.z = hi.x; a.w = hi.y;
        part_s[ty * 512 + c * ROW4 + tx] = a;
    }
    __syncthreads();

    // Fold 4 partials: thread t owns flat [c][col] index t.
    float4 v = f4add(f4add(part_s[t], part_s[t + 512]),
                     f4add(part_s[t + 1024], part_s[t + 1536]));

    // Block GN stats: warp shfl -> 16 warp partials -> redundant sum.
    {
        float ps  = v.x + v.y + v.z + v.w;
        float pss = fmaf(v.x, v.x, fmaf(v.y, v.y,
                    fmaf(v.z, v.z, v.w * v.w)));
        #pragma unroll
        for (int off = 16; off > 0; off >>= 1) {
            ps  += __shfl_xor_sync(0xffffffffu, ps,  off);
            pss += __shfl_xor_sync(0xffffffffu, pss, off);
        }
        const int lane = t & 31, wid = t >> 5;
        if (lane == 0) {
            red_s[wid] = ps;
            red_s[NWARPS + wid] = pss;
        }
    }
    __syncthreads();

    float ts = 0.f, tss = 0.f;
    #pragma unroll
    for (int w = 0; w < NWARPS; w++) {
        ts  += red_s[w];
        tss += red_s[NWARPS + w];
    }
    const float inv_n = 1.0f / (float)(CH_PER_G * NPT);
    const float m     = ts * inv_n;
    const float var   = tss * inv_n - m * m;   // biased (jnp.var)
    const float rst   = rsqrtf(var + EPS_GN);

    // Normalize + ReLU + store: one STG.128 per thread.
    {
        const int c   = t >> 7;
        const int col = t & 127;
        const float ga = gamma[c0 + c] * rst;
        const float be = beta[c0 + c];
        float4 y;
        y.x = fmaxf(fmaf(v.x - m, ga, be), 0.f);
        y.y = fmaxf(fmaf(v.y - m, ga, be), 0.f);
        y.z = fmaxf(fmaf(v.z - m, ga, be), 0.f);
        y.w = fmaxf(fmaf(v.w - m, ga, be), 0.f);
        float4* ob = (float4*)(out + (size_t)b * C_CH * NPT);
        ob[(size_t)(c0 + c) * ROW4 + col] = y;
    }
}

extern "C" void kernel_launch(void* const* d_in, const int* in_sizes, int n_in,
                              void* d_out, int out_size) {
    // metadata order:
    // 0 feat, 1 Wk, 2 bk, 3 Wq, 4 bq, 5 Wv, 6 bv, 7 gn_v_g, 8 gn_v_b,
    // 9 gn1_g, 10 gn1_b, 11 W1, 12 b1, 13 gn2_g, 14 gn2_b, 15 W2, 16 b2
    const float* feat = (const float*)d_in[0];
    const float* Wv   = (const float*)d_in[5];
    const float* bv   = (const float*)d_in[6];
    const float* gn_g = (const float*)d_in[7];
    const float* gn_b = (const float*)d_in[8];
    float* out = (float*)d_out;

    (void)in_sizes; (void)n_in; (void)out_size;

    fused_v_gn_relu_kernel<<<64, NTHREADS>>>(feat, Wv, bv, gn_g, gn_b, out);
}